// round 13
// baseline (speedup 1.0000x reference)
#include <cuda_runtime.h>
#include <math.h>
#include <stdint.h>

// ============================================================================
// TPForth: e3nn-style tensor product, B x (x1[156], x2[9], w[7128]) -> out[156]
// TWO 96-thread half-blocks per row (grid 2B). Type A computes {r0e,r1o},
// type B computes {r1e,r0o}; each TMAs exactly its 3564-float weight half.
// ~16KB smem -> 14 slots/SM. Both halves L2-prefetch their half 256 rows
// ahead. SINGLE KERNEL: each block computes the Wigner-3j tensors in-block
// (hidden under its ~8k-cycle TMA queue delay); no separate init kernel.
// ============================================================================

#define WTOT  7128
#define WHALF 3564
#define XW    156
#define PF_DIST 256

// Global weight offsets (floats): w00@0(48x48) w01@2304(48x10) w10@2784(10x10)
// w110@2884(10x48) w112@3364(10x10) w12@3464(10x10) w20@3564(10x10)
// w211@3664(10x10) w213@3764(10x48) w22@4244(10x10) w30@4344(48x48) w31@6648(48x10)
//
// Type A copies [0,3364)+[3464,3564)+[3664,3764) -> local w00@0 w01@2304
//   w10@2784 w110@2884 w12@3364 w211@3464
// Type B copies [3364,3464)+[3564,3664)+[3764,7128) -> local w112@0 w20@100
//   w213@200 w22@680 w30@780 w31@3084

// ---------------------------------------------------------------------------
// fp32 Wigner-3j pieces (exact replication of the reference construction).
// ---------------------------------------------------------------------------
struct CF { float r, i; };
__device__ __forceinline__ CF cmulf(CF a, CF b) {
    CF c; c.r = a.r*b.r - a.i*b.i; c.i = a.r*b.i + a.i*b.r; return c;
}

__device__ void change_basis_f(int l, CF* q) {
    int n = 2*l + 1;
    for (int a = 0; a < n*n; a++) { q[a].r = 0.f; q[a].i = 0.f; }
    const float rs2 = 0.70710678118654752f;
    for (int m = -l; m < 0; m++) {
        q[(l+m)*n + (l - m)].r =  rs2;
        q[(l+m)*n + (l + m)].i = -rs2;
    }
    q[l*n + l].r = 1.f;
    for (int m = 1; m <= l; m++) {
        float s = (m & 1) ? -1.f : 1.f;
        q[(l+m)*n + (l+m)].r = s * rs2;
        q[(l+m)*n + (l-m)].i = s * rs2;
    }
    CF ph;
    switch (l & 3) {
        case 0: ph.r = 1;  ph.i = 0;  break;
        case 1: ph.r = 0;  ph.i = -1; break;
        case 2: ph.r = -1; ph.i = 0;  break;
        default: ph.r = 0; ph.i = 1;  break;
    }
    for (int a = 0; a < n*n; a++) q[a] = cmulf(q[a], ph);
}

__device__ float cg_f(int j1, int j2, int j3, int m1, int m2, int m3,
                      const float* ft) {
    int vmin = -j1 + j2 + m3;
    if (-j1 + m1 > vmin) vmin = -j1 + m1;
    if (0 > vmin) vmin = 0;
    int vmax = j2 + j3 + m1;
    if (j3 - j1 + j2 < vmax) vmax = j3 - j1 + j2;
    if (j3 + m3 < vmax) vmax = j3 + m3;
    float C = sqrtf((2.f*j3 + 1.f) * ft[j3+j1-j2] * ft[j3-j1+j2] * ft[j1+j2-j3]
                    * ft[j3+m3] * ft[j3-m3]
                    / (ft[j1+j2+j3+1] * ft[j1-m1] * ft[j1+m1]
                       * ft[j2-m2] * ft[j2+m2]));
    float S = 0.f;
    for (int v = vmin; v <= vmax; v++) {
        float sgn = ((v + j2 + m2) & 1) ? -1.f : 1.f;
        S += sgn * ft[j2+j3+m1-v] * ft[j1-m1+v]
             / (ft[v] * ft[j3-j1+j2-v] * ft[j3+m3-v] * ft[v+j1-j2-m3]);
    }
    return C * S;
}

// ---------------------------------------------------------------------------
__device__ __forceinline__ uint32_t smem_u32(const void* p) {
    uint32_t a;
    asm("{ .reg .u64 t; cvta.to.shared.u64 t, %1; cvt.u32.u64 %0, t; }"
        : "=r"(a) : "l"(p));
    return a;
}

__device__ __forceinline__ void bulk_cp(uint32_t dst, const float* src,
                                        uint32_t bytes, uint32_t mb) {
    asm volatile(
        "cp.async.bulk.shared::cluster.global.mbarrier::complete_tx::bytes "
        "[%0], [%1], %2, [%3];"
        :: "r"(dst), "l"(src), "r"(bytes), "r"(mb) : "memory");
}

struct __align__(128) SmemLayout {
    float sw[WHALF];                // 14256 B, TMA destination
    float sx1[108];
    float sx2[12];
    float da[10];                   // A: d110   B: d213
    float ca[30];                   // A: c12    B: c112
    float cb[32];                   // A: c211   B: c22
    float sj1[27], sj2[45];         // UNNORMALIZED w3j elements (per block)
    CF    qa[9], qb[25];
    float cg111[9], cg121[15];
    float inv111, inv121;
    uint64_t mbar;
};

__global__ __launch_bounds__(96, 14) void tp_kernel(
    const float* __restrict__ x1,
    const float* __restrict__ x2,
    const float* __restrict__ w,
    float* __restrict__ out,
    int nrows)
{
    extern __shared__ __align__(128) char smem_raw[];
    SmemLayout* S = reinterpret_cast<SmemLayout*>(smem_raw);

    const int tid = threadIdx.x;
    const size_t z = (size_t)(blockIdx.x >> 1);
    const bool isA = (blockIdx.x & 1u) == 0u;

    const uint32_t mbar_a = smem_u32(&S->mbar);
    const float* wrow = w + z * WTOT;

    // ---- tid 0: issue this half's 3 bulk copies at cycle 0 ----
    if (tid == 0) {
        asm volatile("mbarrier.init.shared.b64 [%0], %1;"
                     :: "r"(mbar_a), "r"(1) : "memory");
        asm volatile("fence.proxy.async.shared::cta;" ::: "memory");
        asm volatile("mbarrier.arrive.expect_tx.shared.b64 _, [%0], %1;"
                     :: "r"(mbar_a), "r"((uint32_t)(WHALF * 4)) : "memory");
        uint32_t sws = smem_u32(S->sw);
        if (isA) {
            bulk_cp(sws,             wrow,        3364u * 4u, mbar_a);
            bulk_cp(sws + 3364u*4u,  wrow + 3464,  100u * 4u, mbar_a);
            bulk_cp(sws + 3464u*4u,  wrow + 3664,  100u * 4u, mbar_a);
        } else {
            bulk_cp(sws,             wrow + 3364,  100u * 4u, mbar_a);
            bulk_cp(sws +  100u*4u,  wrow + 3564,  100u * 4u, mbar_a);
            bulk_cp(sws +  200u*4u,  wrow + 3764, 3364u * 4u, mbar_a);
        }
    }

    // ---- Dependency-free L2 prefetch of own half, PF_DIST rows ahead ----
    if (tid == 95 && z + PF_DIST < (size_t)nrows) {
        const float* pf = w + (z + PF_DIST) * WTOT + (isA ? 0 : WHALF);
        asm volatile("cp.async.bulk.prefetch.L2.global [%0], %1;"
                     :: "l"(pf), "r"((uint32_t)(WHALF * 4)) : "memory");
    }

    // ---- Phase A: operand loads + Q matrices + CG tables (under the TMA) ----
    // A keeps x1[0:108) (0e,1o,1e); B keeps x1[48:156) (1o,1e,0o).
    if (tid < 27) {
        const float4* src = reinterpret_cast<const float4*>(x1)
                          + (z * XW + (isA ? 0 : 48)) / 4;
        reinterpret_cast<float4*>(S->sx1)[tid] = src[tid];
    } else if (tid >= 32 && tid < 41) {
        S->sx2[tid - 32] = x2[z * 9 + (tid - 32)];
    } else if (tid >= 48 && tid < 57) {
        // cg111[i*3+k] = <1 m1 1 m2 | 1 m3>, 0 when |m3|>1
        float ft[8];
        ft[0] = 1.f;
        for (int k = 1; k < 8; k++) ft[k] = ft[k-1] * (float)k;
        int t = tid - 48, i = t / 3, k = t % 3;
        int m1 = i - 1, m2 = k - 1, m3 = m1 + m2;
        S->cg111[t] = (m3 >= -1 && m3 <= 1) ? cg_f(1, 1, 1, m1, m2, m3, ft) : 0.f;
    } else if (tid >= 57 && tid < 72) {
        float ft[8];
        ft[0] = 1.f;
        for (int k = 1; k < 8; k++) ft[k] = ft[k-1] * (float)k;
        int t = tid - 57, i = t / 5, k = t % 5;
        int m1 = i - 1, m2 = k - 2, m3 = m1 + m2;
        S->cg121[t] = (m3 >= -1 && m3 <= 1) ? cg_f(1, 2, 1, m1, m2, m3, ft) : 0.f;
    } else if (tid == 80) {
        change_basis_f(1, S->qa);
    } else if (tid == 81) {
        change_basis_f(2, S->qb);
    }
    __syncthreads();

    const float* px1 = S->sx1;
    const float* px2 = S->sx2;

    // ---- Phase B: w3j elements (unnormalized) + da ----
    if (tid < 27) {
        int j = tid / 9, l = (tid % 9) / 3, m = tid % 3;
        float acc = 0.f;
        for (int i = 0; i < 3; i++) {
            for (int k = 0; k < 3; k++) {
                int n = i + k - 1;
                if (n < 0 || n > 2) continue;
                float cgv = S->cg111[i*3 + k];
                if (cgv == 0.f) continue;
                CF t = cmulf(S->qa[i*3 + j], S->qa[k*3 + l]);
                CF c3; c3.r = S->qa[n*3 + m].r; c3.i = -S->qa[n*3 + m].i;
                t = cmulf(t, c3);
                acc += t.r * cgv;
            }
        }
        S->sj1[tid] = acc;
    } else if (tid >= 32 && tid < 77) {
        int t0 = tid - 32;
        int j = t0 / 15, l = (t0 % 15) / 3, m = t0 % 3;
        float acc = 0.f;
        for (int i = 0; i < 3; i++) {
            for (int k = 0; k < 5; k++) {
                int n = i + k - 2;
                if (n < 0 || n > 2) continue;
                float cgv = S->cg121[i*5 + k];
                if (cgv == 0.f) continue;
                CF t = cmulf(S->qa[i*3 + j], S->qb[k*5 + l]);
                CF c3; c3.r = S->qa[n*3 + m].r; c3.i = -S->qa[n*3 + m].i;
                t = cmulf(t, c3);
                acc += t.r * cgv;
            }
        }
        S->sj2[t0] = acc;
    } else if (tid >= 78 && tid < 88) {
        // da: A: d110 = x1_1o . x2_1o   B: d213 = x1_1e . x2_1o
        int u = tid - 78;
        const float* p = isA ? (px1 + 48) : (px1 + 30);
        float v = 0.f;
        #pragma unroll
        for (int q = 0; q < 3; q++) v += p[u*3 + q] * px2[1 + q];
        S->da[u] = v;
    }
    __syncthreads();

    // ---- Phase C: norms ----
    if (tid == 0) {
        float s = 0.f;
        for (int a = 0; a < 27; a++) s += S->sj1[a] * S->sj1[a];
        S->inv111 = rsqrtf(s);
    } else if (tid == 1) {
        float s = 0.f;
        for (int a = 0; a < 45; a++) s += S->sj2[a] * S->sj2[a];
        S->inv121 = rsqrtf(s);
    }
    __syncthreads();

    // ---- Phase D: aux coefficients (scaled by the deferred norm) ----
    // A: ca=c12 (sj2,inv121)  cb=c211 (sj1,inv111)
    // B: ca=c112 (sj1,inv111) cb=c22  (sj2,inv121)
    if (tid < 30) {
        int u = tid/3, k = tid%3; float v = 0.f;
        if (isA) {      // c12: x1_1o @48, x2_2e, sj2
            #pragma unroll
            for (int q = 0; q < 3; q++)
                #pragma unroll
                for (int j = 0; j < 5; j++)
                    v += px1[48 + u*3 + q] * px2[4 + j] * S->sj2[q*15 + j*3 + k];
            v *= S->inv121;
        } else {        // c112: x1_1o @0, x2_1o, sj1
            #pragma unroll
            for (int q = 0; q < 3; q++)
                #pragma unroll
                for (int j = 0; j < 3; j++)
                    v += px1[u*3 + q] * px2[1 + j] * S->sj1[q*9 + j*3 + k];
            v *= S->inv111;
        }
        S->ca[tid] = v;
    } else if (tid < 60) {
        int t = tid - 30, u = t/3, k = t%3; float v = 0.f;
        if (isA) {      // c211: x1_1e @78, x2_1o, sj1
            #pragma unroll
            for (int q = 0; q < 3; q++)
                #pragma unroll
                for (int j = 0; j < 3; j++)
                    v += px1[78 + u*3 + q] * px2[1 + j] * S->sj1[q*9 + j*3 + k];
            v *= S->inv111;
        } else {        // c22: x1_1e @30, x2_2e, sj2
            #pragma unroll
            for (int q = 0; q < 3; q++)
                #pragma unroll
                for (int j = 0; j < 5; j++)
                    v += px1[30 + u*3 + q] * px2[4 + j] * S->sj2[q*15 + j*3 + k];
            v *= S->inv121;
        }
        S->cb[t] = v;
    }
    __syncthreads();

    // ---- Wait for weights ----
    {
        uint32_t done;
        do {
            asm volatile(
                "{\n .reg .pred p;\n"
                " mbarrier.try_wait.parity.acquire.cta.shared::cta.b64 p, [%1], %2, 0x989680;\n"
                " selp.b32 %0, 1, 0, p;\n}"
                : "=r"(done) : "r"(mbar_a), "r"(0u) : "memory");
        } while (!done);
    }

    const float NORM_0E = 0.13130643285972254f;  // sqrt(1/58)
    const float NORM_1O = 0.19611613513818404f;  // sqrt(3/78)
    const float NORM_1E = 0.19611613513818404f;
    const float NORM_0O = 0.13130643285972254f;
    const float RS3     = 0.57735026918962576f;

    const float* sw = S->sw;
    float* orow = out + z * XW;

    if (isA) {
        if (tid < 48) {
            // r0e[w]: w00@0, w110@2884
            float a = 0.f;
            #pragma unroll 8
            for (int u = 0; u < 48; u++) a += px1[u] * sw[u*48 + tid];
            float bb = 0.f;
            #pragma unroll
            for (int u = 0; u < 10; u++) bb += S->da[u] * sw[2884 + u*48 + tid];
            orow[tid] = NORM_0E * (a * px2[0] + RS3 * bb);
        } else if (tid < 78) {
            // r1o[w,i]: w01@2304, w10@2784, w12@3364(local), w211@3464(local)
            int t = tid - 48, wI = t/3, i = t%3;
            float t01 = 0.f;
            #pragma unroll 8
            for (int u = 0; u < 48; u++) t01 += px1[u] * sw[2304 + u*10 + wI];
            float a10 = 0.f, a12 = 0.f, a211 = 0.f;
            #pragma unroll
            for (int u = 0; u < 10; u++) {
                a10  += px1[48 + u*3 + i] * sw[2784 + u*10 + wI];
                a12  += S->ca[u*3 + i]    * sw[3364 + u*10 + wI];
                a211 += S->cb[u*3 + i]    * sw[3464 + u*10 + wI];
            }
            orow[48 + wI*3 + i] =
                NORM_1O * (RS3 * (t01 * px2[1 + i] + px2[0] * a10) + a12 + a211);
        }
    } else {
        if (tid < 30) {
            // r1e[w,k]: w112@0, w20@100, w22@680, w31@3084 (local)
            int wI = tid/3, k = tid%3;
            float t31 = 0.f;
            #pragma unroll 8
            for (int u = 0; u < 48; u++) t31 += px1[60 + u] * sw[3084 + u*10 + wI];
            float a112 = 0.f, a20 = 0.f, a22 = 0.f;
            #pragma unroll
            for (int u = 0; u < 10; u++) {
                a112 += S->ca[u*3 + k]    * sw[u*10 + wI];
                a20  += px1[30 + u*3 + k] * sw[100 + u*10 + wI];
                a22  += S->cb[u*3 + k]    * sw[680 + u*10 + wI];
            }
            orow[78 + wI*3 + k] =
                NORM_1E * (a112 + RS3 * (px2[0] * a20 + t31 * px2[1 + k]) + a22);
        } else if (tid < 78) {
            // r0o[w]: w213@200, w30@780 (local); x1_0o @ px1[60]
            int wI = tid - 30;
            float a = 0.f;
            #pragma unroll
            for (int u = 0; u < 10; u++) a += S->da[u] * sw[200 + u*48 + wI];
            float bb = 0.f;
            #pragma unroll 8
            for (int u = 0; u < 48; u++) bb += px1[60 + u] * sw[780 + u*48 + wI];
            orow[108 + wI] = NORM_0O * (RS3 * a + bb * px2[0]);
        }
    }
}

// ---------------------------------------------------------------------------
extern "C" void kernel_launch(void* const* d_in, const int* in_sizes, int n_in,
                              void* d_out, int out_size)
{
    const float* x1 = (const float*)d_in[0];
    const float* x2 = (const float*)d_in[1];
    const float* w  = (const float*)d_in[2];
    float* out = (float*)d_out;

    int B = in_sizes[1] / 9;   // x2 has 9 floats per row
    int smem_bytes = (int)sizeof(SmemLayout);

    cudaFuncSetAttribute(tp_kernel,
                         cudaFuncAttributeMaxDynamicSharedMemorySize, smem_bytes);

    tp_kernel<<<2 * B, 96, smem_bytes>>>(x1, x2, w, out, B);
}

// round 14
// speedup vs baseline: 1.2891x; 1.2891x over previous
#include <cuda_runtime.h>
#include <math.h>
#include <stdint.h>

// ============================================================================
// TPForth: e3nn-style tensor product, B x (x1[156], x2[9], w[7128]) -> out[156]
// TWO 96-thread half-blocks per row (grid 2B). Type A computes {r0e,r1o},
// type B computes {r1e,r0o}; each TMAs exactly its 3564-float weight half.
// ~16KB smem -> 14 slots/SM. Both halves L2-prefetch their half 256 rows
// ahead. Wigner-3j tensors are computed at COMPILE TIME (constexpr fp64
// replication of the reference construction) into __constant__ arrays:
// no init kernel, no per-block recompute.
// ============================================================================

#define WTOT  7128
#define WHALF 3564
#define XW    156
#define PF_DIST 256

// Global weight offsets (floats): w00@0(48x48) w01@2304(48x10) w10@2784(10x10)
// w110@2884(10x48) w112@3364(10x10) w12@3464(10x10) w20@3564(10x10)
// w211@3664(10x10) w213@3764(10x48) w22@4244(10x10) w30@4344(48x48) w31@6648(48x10)
//
// Type A copies [0,3364)+[3464,3564)+[3664,3764) -> local w00@0 w01@2304
//   w10@2784 w110@2884 w12@3364 w211@3464
// Type B copies [3364,3464)+[3564,3664)+[3764,7128) -> local w112@0 w20@100
//   w213@200 w22@680 w30@780 w31@3084

// ---------------------------------------------------------------------------
// Compile-time Wigner-3j (exact fp64 replication of the reference recipe).
// ---------------------------------------------------------------------------
constexpr double csqrt_(double x) {
    double g = (x > 1.0) ? x : 1.0;
    for (int it = 0; it < 64; ++it) g = 0.5 * (g + x / g);
    return g;
}
constexpr double dfact_(int n) {
    double r = 1.0;
    for (int k = 2; k <= n; ++k) r *= (double)k;
    return r;
}

struct CD { double r, i; };
constexpr CD cmul_(CD a, CD b) {
    return CD{a.r*b.r - a.i*b.i, a.r*b.i + a.i*b.r};
}

struct QM { CD q[25]; };

constexpr QM change_basis_(int l) {
    QM Q{};
    int n = 2*l + 1;
    double rs2 = 1.0 / csqrt_(2.0);
    for (int m = -l; m < 0; ++m) {
        Q.q[(l+m)*n + (l - m)].r =  rs2;
        Q.q[(l+m)*n + (l + m)].i = -rs2;
    }
    Q.q[l*n + l].r = 1.0;
    for (int m = 1; m <= l; ++m) {
        double s = (m & 1) ? -1.0 : 1.0;
        Q.q[(l+m)*n + (l+m)].r = s * rs2;
        Q.q[(l+m)*n + (l-m)].i = s * rs2;
    }
    CD ph{1.0, 0.0};
    switch (l & 3) {              // (-i)^l
        case 0: ph = CD{ 1.0,  0.0}; break;
        case 1: ph = CD{ 0.0, -1.0}; break;
        case 2: ph = CD{-1.0,  0.0}; break;
        default: ph = CD{ 0.0,  1.0}; break;
    }
    for (int a = 0; a < n*n; ++a) Q.q[a] = cmul_(Q.q[a], ph);
    return Q;
}

constexpr double cg_(int j1, int j2, int j3, int m1, int m2, int m3) {
    int vmin = -j1 + j2 + m3;
    if (-j1 + m1 > vmin) vmin = -j1 + m1;
    if (0 > vmin) vmin = 0;
    int vmax = j2 + j3 + m1;
    if (j3 - j1 + j2 < vmax) vmax = j3 - j1 + j2;
    if (j3 + m3 < vmax) vmax = j3 + m3;
    double C = csqrt_((2.0*j3 + 1.0) * dfact_(j3+j1-j2) * dfact_(j3-j1+j2)
                      * dfact_(j1+j2-j3) * dfact_(j3+m3) * dfact_(j3-m3)
                      / (dfact_(j1+j2+j3+1) * dfact_(j1-m1) * dfact_(j1+m1)
                         * dfact_(j2-m2) * dfact_(j2+m2)));
    double S = 0.0;
    for (int v = vmin; v <= vmax; ++v) {
        double sgn = ((v + j2 + m2) & 1) ? -1.0 : 1.0;
        S += sgn * dfact_(j2+j3+m1-v) * dfact_(j1-m1+v)
             / (dfact_(v) * dfact_(j3-j1+j2-v) * dfact_(j3+m3-v)
                * dfact_(v+j1-j2-m3));
    }
    return C * S;
}

// Unnormalized element C[j,l,m] of wigner_3j(l1,l2,l3).
constexpr double w3j_elem_(int l1, int l2, int l3, int j, int l, int m) {
    QM Q1 = change_basis_(l1);
    QM Q2 = change_basis_(l2);
    QM Q3 = change_basis_(l3);
    int n1 = 2*l1+1, n2 = 2*l2+1, n3 = 2*l3+1;
    double acc = 0.0;
    for (int i = 0; i < n1; ++i) {
        for (int k = 0; k < n2; ++k) {
            int m3v = (i - l1) + (k - l2);
            if (m3v < -l3 || m3v > l3) continue;
            int nn = l3 + m3v;
            double cgv = cg_(l1, l2, l3, i - l1, k - l2, m3v);
            CD t = cmul_(Q1.q[i*n1 + j], Q2.q[k*n2 + l]);
            CD c3{Q3.q[nn*n3 + m].r, -Q3.q[nn*n3 + m].i};
            t = cmul_(t, c3);
            acc += t.r * cgv;
        }
    }
    return acc;
}

constexpr double w3j_norm_(int l1, int l2, int l3) {
    int n1 = 2*l1+1, n2 = 2*l2+1, n3 = 2*l3+1;
    double s = 0.0;
    for (int j = 0; j < n1; ++j)
        for (int l = 0; l < n2; ++l)
            for (int m = 0; m < n3; ++m) {
                double e = w3j_elem_(l1, l2, l3, j, l, m);
                s += e * e;
            }
    return csqrt_(s);
}

constexpr double N111_ = w3j_norm_(1, 1, 1);
constexpr double N121_ = w3j_norm_(1, 2, 1);

constexpr float W111(int idx) {
    return (float)(w3j_elem_(1, 1, 1, idx/9, (idx%9)/3, idx%3) / N111_);
}
constexpr float W121(int idx) {
    return (float)(w3j_elem_(1, 2, 1, idx/15, (idx%15)/3, idx%3) / N121_);
}

__constant__ float c_w3j111[27] = {
    W111(0),  W111(1),  W111(2),  W111(3),  W111(4),  W111(5),  W111(6),
    W111(7),  W111(8),  W111(9),  W111(10), W111(11), W111(12), W111(13),
    W111(14), W111(15), W111(16), W111(17), W111(18), W111(19), W111(20),
    W111(21), W111(22), W111(23), W111(24), W111(25), W111(26)
};
__constant__ float c_w3j121[45] = {
    W121(0),  W121(1),  W121(2),  W121(3),  W121(4),  W121(5),  W121(6),
    W121(7),  W121(8),  W121(9),  W121(10), W121(11), W121(12), W121(13),
    W121(14), W121(15), W121(16), W121(17), W121(18), W121(19), W121(20),
    W121(21), W121(22), W121(23), W121(24), W121(25), W121(26), W121(27),
    W121(28), W121(29), W121(30), W121(31), W121(32), W121(33), W121(34),
    W121(35), W121(36), W121(37), W121(38), W121(39), W121(40), W121(41),
    W121(42), W121(43), W121(44)
};

// ---------------------------------------------------------------------------
__device__ __forceinline__ uint32_t smem_u32(const void* p) {
    uint32_t a;
    asm("{ .reg .u64 t; cvta.to.shared.u64 t, %1; cvt.u32.u64 %0, t; }"
        : "=r"(a) : "l"(p));
    return a;
}

__device__ __forceinline__ void bulk_cp(uint32_t dst, const float* src,
                                        uint32_t bytes, uint32_t mb) {
    asm volatile(
        "cp.async.bulk.shared::cluster.global.mbarrier::complete_tx::bytes "
        "[%0], [%1], %2, [%3];"
        :: "r"(dst), "l"(src), "r"(bytes), "r"(mb) : "memory");
}

struct __align__(128) SmemLayout {
    float sw[WHALF];                // 14256 B, TMA destination
    float sx1[108];
    float sx2[12];
    float da[10];                   // A: d110   B: d213
    float ca[30];                   // A: c12    B: c112
    float cb[32];                   // A: c211   B: c22
    float sj1[27], sj2[45];
    uint64_t mbar;
};

__global__ __launch_bounds__(96, 14) void tp_kernel(
    const float* __restrict__ x1,
    const float* __restrict__ x2,
    const float* __restrict__ w,
    float* __restrict__ out,
    int nrows)
{
    extern __shared__ __align__(128) char smem_raw[];
    SmemLayout* S = reinterpret_cast<SmemLayout*>(smem_raw);

    const int tid = threadIdx.x;
    const size_t z = (size_t)(blockIdx.x >> 1);
    const bool isA = (blockIdx.x & 1u) == 0u;

    const uint32_t mbar_a = smem_u32(&S->mbar);
    const float* wrow = w + z * WTOT;

    // ---- tid 0: issue this half's 3 bulk copies at cycle 0 ----
    if (tid == 0) {
        asm volatile("mbarrier.init.shared.b64 [%0], %1;"
                     :: "r"(mbar_a), "r"(1) : "memory");
        asm volatile("fence.proxy.async.shared::cta;" ::: "memory");
        asm volatile("mbarrier.arrive.expect_tx.shared.b64 _, [%0], %1;"
                     :: "r"(mbar_a), "r"((uint32_t)(WHALF * 4)) : "memory");
        uint32_t sws = smem_u32(S->sw);
        if (isA) {
            bulk_cp(sws,             wrow,        3364u * 4u, mbar_a);
            bulk_cp(sws + 3364u*4u,  wrow + 3464,  100u * 4u, mbar_a);
            bulk_cp(sws + 3464u*4u,  wrow + 3664,  100u * 4u, mbar_a);
        } else {
            bulk_cp(sws,             wrow + 3364,  100u * 4u, mbar_a);
            bulk_cp(sws +  100u*4u,  wrow + 3564,  100u * 4u, mbar_a);
            bulk_cp(sws +  200u*4u,  wrow + 3764, 3364u * 4u, mbar_a);
        }
    }

    // ---- Dependency-free L2 prefetch of own half, PF_DIST rows ahead ----
    if (tid == 95 && z + PF_DIST < (size_t)nrows) {
        const float* pf = w + (z + PF_DIST) * WTOT + (isA ? 0 : WHALF);
        asm volatile("cp.async.bulk.prefetch.L2.global [%0], %1;"
                     :: "l"(pf), "r"((uint32_t)(WHALF * 4)) : "memory");
    }

    // ---- Small operand loads in parallel with the TMA ----
    // A keeps x1[0:108) (0e,1o,1e); B keeps x1[48:156) (1o,1e,0o).
    if (tid < 27) {
        const float4* src = reinterpret_cast<const float4*>(x1)
                          + (z * XW + (isA ? 0 : 48)) / 4;
        reinterpret_cast<float4*>(S->sx1)[tid] = src[tid];
    } else if (tid >= 32 && tid < 41) {
        S->sx2[tid - 32] = x2[z * 9 + (tid - 32)];
    }
    if (tid >= 48 && tid < 75)  S->sj1[tid - 48] = c_w3j111[tid - 48];
    if (tid >= 48 && tid < 93)  S->sj2[tid - 48] = c_w3j121[tid - 48];
    __syncthreads();

    const float* px1 = S->sx1;
    const float* px2 = S->sx2;

    // ---- Aux coefficients (under the TMA) ----
    // A: da=d110(x1_1o.x2_1o) ca=c12(x1_1o ox x2_2e) cb=c211(x1_1e ox x2_1o)
    // B: da=d213(x1_1e.x2_1o) ca=c112(x1_1o ox x2_1o) cb=c22(x1_1e ox x2_2e)
    if (tid < 10) {
        const float* p = isA ? (px1 + 48) : (px1 + 30);   // 1o vs 1e base
        float v = 0.f;
        #pragma unroll
        for (int q = 0; q < 3; q++) v += p[tid*3 + q] * px2[1 + q];
        S->da[tid] = v;
    } else if (tid < 40) {
        int t = tid - 10, u = t/3, k = t%3; float v = 0.f;
        if (isA) {      // c12: x1_1o @48, x2_2e, sj2
            #pragma unroll
            for (int q = 0; q < 3; q++)
                #pragma unroll
                for (int j = 0; j < 5; j++)
                    v += px1[48 + u*3 + q] * px2[4 + j] * S->sj2[q*15 + j*3 + k];
        } else {        // c112: x1_1o @0, x2_1o, sj1
            #pragma unroll
            for (int q = 0; q < 3; q++)
                #pragma unroll
                for (int j = 0; j < 3; j++)
                    v += px1[u*3 + q] * px2[1 + j] * S->sj1[q*9 + j*3 + k];
        }
        S->ca[t] = v;
    } else if (tid < 70) {
        int t = tid - 40, u = t/3, k = t%3; float v = 0.f;
        if (isA) {      // c211: x1_1e @78, x2_1o, sj1
            #pragma unroll
            for (int q = 0; q < 3; q++)
                #pragma unroll
                for (int j = 0; j < 3; j++)
                    v += px1[78 + u*3 + q] * px2[1 + j] * S->sj1[q*9 + j*3 + k];
        } else {        // c22: x1_1e @30, x2_2e, sj2
            #pragma unroll
            for (int q = 0; q < 3; q++)
                #pragma unroll
                for (int j = 0; j < 5; j++)
                    v += px1[30 + u*3 + q] * px2[4 + j] * S->sj2[q*15 + j*3 + k];
        }
        S->cb[t] = v;
    }
    __syncthreads();

    // ---- Wait for weights ----
    {
        uint32_t done;
        do {
            asm volatile(
                "{\n .reg .pred p;\n"
                " mbarrier.try_wait.parity.acquire.cta.shared::cta.b64 p, [%1], %2, 0x989680;\n"
                " selp.b32 %0, 1, 0, p;\n}"
                : "=r"(done) : "r"(mbar_a), "r"(0u) : "memory");
        } while (!done);
    }

    const float NORM_0E = 0.13130643285972254f;  // sqrt(1/58)
    const float NORM_1O = 0.19611613513818404f;  // sqrt(3/78)
    const float NORM_1E = 0.19611613513818404f;
    const float NORM_0O = 0.13130643285972254f;
    const float RS3     = 0.57735026918962576f;  // 1/sqrt(3)

    const float* sw = S->sw;
    float* orow = out + z * XW;

    if (isA) {
        if (tid < 48) {
            // r0e[w]: w00@0, w110@2884
            float a = 0.f;
            #pragma unroll 8
            for (int u = 0; u < 48; u++) a += px1[u] * sw[u*48 + tid];
            float bb = 0.f;
            #pragma unroll
            for (int u = 0; u < 10; u++) bb += S->da[u] * sw[2884 + u*48 + tid];
            orow[tid] = NORM_0E * (a * px2[0] + RS3 * bb);
        } else if (tid < 78) {
            // r1o[w,i]: w01@2304, w10@2784, w12@3364(local), w211@3464(local)
            int t = tid - 48, wI = t/3, i = t%3;
            float t01 = 0.f;
            #pragma unroll 8
            for (int u = 0; u < 48; u++) t01 += px1[u] * sw[2304 + u*10 + wI];
            float a10 = 0.f, a12 = 0.f, a211 = 0.f;
            #pragma unroll
            for (int u = 0; u < 10; u++) {
                a10  += px1[48 + u*3 + i] * sw[2784 + u*10 + wI];
                a12  += S->ca[u*3 + i]    * sw[3364 + u*10 + wI];
                a211 += S->cb[u*3 + i]    * sw[3464 + u*10 + wI];
            }
            orow[48 + wI*3 + i] =
                NORM_1O * (RS3 * (t01 * px2[1 + i] + px2[0] * a10) + a12 + a211);
        }
    } else {
        if (tid < 30) {
            // r1e[w,k]: w112@0, w20@100, w22@680, w31@3084 (local)
            int wI = tid/3, k = tid%3;
            float t31 = 0.f;
            #pragma unroll 8
            for (int u = 0; u < 48; u++) t31 += px1[60 + u] * sw[3084 + u*10 + wI];
            float a112 = 0.f, a20 = 0.f, a22 = 0.f;
            #pragma unroll
            for (int u = 0; u < 10; u++) {
                a112 += S->ca[u*3 + k]    * sw[u*10 + wI];
                a20  += px1[30 + u*3 + k] * sw[100 + u*10 + wI];
                a22  += S->cb[u*3 + k]    * sw[680 + u*10 + wI];
            }
            orow[78 + wI*3 + k] =
                NORM_1E * (a112 + RS3 * (px2[0] * a20 + t31 * px2[1 + k]) + a22);
        } else if (tid < 78) {
            // r0o[w]: w213@200, w30@780 (local); x1_0o @ px1[60]
            int wI = tid - 30;
            float a = 0.f;
            #pragma unroll
            for (int u = 0; u < 10; u++) a += S->da[u] * sw[200 + u*48 + wI];
            float bb = 0.f;
            #pragma unroll 8
            for (int u = 0; u < 48; u++) bb += px1[60 + u] * sw[780 + u*48 + wI];
            orow[108 + wI] = NORM_0O * (RS3 * a + bb * px2[0]);
        }
    }
}

// ---------------------------------------------------------------------------
extern "C" void kernel_launch(void* const* d_in, const int* in_sizes, int n_in,
                              void* d_out, int out_size)
{
    const float* x1 = (const float*)d_in[0];
    const float* x2 = (const float*)d_in[1];
    const float* w  = (const float*)d_in[2];
    float* out = (float*)d_out;

    int B = in_sizes[1] / 9;   // x2 has 9 floats per row
    int smem_bytes = (int)sizeof(SmemLayout);

    cudaFuncSetAttribute(tp_kernel,
                         cudaFuncAttributeMaxDynamicSharedMemorySize, smem_bytes);

    tp_kernel<<<2 * B, 96, smem_bytes>>>(x1, x2, w, out, B);
}

// round 15
// speedup vs baseline: 1.3030x; 1.0108x over previous
#include <cuda_runtime.h>
#include <math.h>
#include <stdint.h>

// ============================================================================
// TPForth: e3nn-style tensor product, B x (x1[156], x2[9], w[7128]) -> out[156]
// TWO 96-thread half-blocks per row (grid 2B). Type A computes {r0e,r1o},
// type B computes {r1e,r0o}; each TMAs exactly its 3564-float weight half.
// 15360B smem -> 15 slots/SM (launch_bounds(96,15)). Both halves L2-prefetch
// their half 256 rows ahead. Wigner-3j computed at COMPILE TIME (constexpr
// fp64 replication of the reference construction) into __constant__ arrays.
// ============================================================================

#define WTOT  7128
#define WHALF 3564
#define XW    156
#define PF_DIST 256

// Global weight offsets (floats): w00@0(48x48) w01@2304(48x10) w10@2784(10x10)
// w110@2884(10x48) w112@3364(10x10) w12@3464(10x10) w20@3564(10x10)
// w211@3664(10x10) w213@3764(10x48) w22@4244(10x10) w30@4344(48x48) w31@6648(48x10)
//
// Type A copies [0,3364)+[3464,3564)+[3664,3764) -> local w00@0 w01@2304
//   w10@2784 w110@2884 w12@3364 w211@3464
// Type B copies [3364,3464)+[3564,3664)+[3764,7128) -> local w112@0 w20@100
//   w213@200 w22@680 w30@780 w31@3084

// ---------------------------------------------------------------------------
// Compile-time Wigner-3j (exact fp64 replication of the reference recipe).
// ---------------------------------------------------------------------------
constexpr double csqrt_(double x) {
    double g = (x > 1.0) ? x : 1.0;
    for (int it = 0; it < 64; ++it) g = 0.5 * (g + x / g);
    return g;
}
constexpr double dfact_(int n) {
    double r = 1.0;
    for (int k = 2; k <= n; ++k) r *= (double)k;
    return r;
}

struct CD { double r, i; };
constexpr CD cmul_(CD a, CD b) {
    return CD{a.r*b.r - a.i*b.i, a.r*b.i + a.i*b.r};
}

struct QM { CD q[25]; };

constexpr QM change_basis_(int l) {
    QM Q{};
    int n = 2*l + 1;
    double rs2 = 1.0 / csqrt_(2.0);
    for (int m = -l; m < 0; ++m) {
        Q.q[(l+m)*n + (l - m)].r =  rs2;
        Q.q[(l+m)*n + (l + m)].i = -rs2;
    }
    Q.q[l*n + l].r = 1.0;
    for (int m = 1; m <= l; ++m) {
        double s = (m & 1) ? -1.0 : 1.0;
        Q.q[(l+m)*n + (l+m)].r = s * rs2;
        Q.q[(l+m)*n + (l-m)].i = s * rs2;
    }
    CD ph{1.0, 0.0};
    switch (l & 3) {              // (-i)^l
        case 0: ph = CD{ 1.0,  0.0}; break;
        case 1: ph = CD{ 0.0, -1.0}; break;
        case 2: ph = CD{-1.0,  0.0}; break;
        default: ph = CD{ 0.0,  1.0}; break;
    }
    for (int a = 0; a < n*n; ++a) Q.q[a] = cmul_(Q.q[a], ph);
    return Q;
}

constexpr double cg_(int j1, int j2, int j3, int m1, int m2, int m3) {
    int vmin = -j1 + j2 + m3;
    if (-j1 + m1 > vmin) vmin = -j1 + m1;
    if (0 > vmin) vmin = 0;
    int vmax = j2 + j3 + m1;
    if (j3 - j1 + j2 < vmax) vmax = j3 - j1 + j2;
    if (j3 + m3 < vmax) vmax = j3 + m3;
    double C = csqrt_((2.0*j3 + 1.0) * dfact_(j3+j1-j2) * dfact_(j3-j1+j2)
                      * dfact_(j1+j2-j3) * dfact_(j3+m3) * dfact_(j3-m3)
                      / (dfact_(j1+j2+j3+1) * dfact_(j1-m1) * dfact_(j1+m1)
                         * dfact_(j2-m2) * dfact_(j2+m2)));
    double S = 0.0;
    for (int v = vmin; v <= vmax; ++v) {
        double sgn = ((v + j2 + m2) & 1) ? -1.0 : 1.0;
        S += sgn * dfact_(j2+j3+m1-v) * dfact_(j1-m1+v)
             / (dfact_(v) * dfact_(j3-j1+j2-v) * dfact_(j3+m3-v)
                * dfact_(v+j1-j2-m3));
    }
    return C * S;
}

// Unnormalized element C[j,l,m] of wigner_3j(l1,l2,l3).
constexpr double w3j_elem_(int l1, int l2, int l3, int j, int l, int m) {
    QM Q1 = change_basis_(l1);
    QM Q2 = change_basis_(l2);
    QM Q3 = change_basis_(l3);
    int n1 = 2*l1+1, n2 = 2*l2+1, n3 = 2*l3+1;
    double acc = 0.0;
    for (int i = 0; i < n1; ++i) {
        for (int k = 0; k < n2; ++k) {
            int m3v = (i - l1) + (k - l2);
            if (m3v < -l3 || m3v > l3) continue;
            int nn = l3 + m3v;
            double cgv = cg_(l1, l2, l3, i - l1, k - l2, m3v);
            CD t = cmul_(Q1.q[i*n1 + j], Q2.q[k*n2 + l]);
            CD c3{Q3.q[nn*n3 + m].r, -Q3.q[nn*n3 + m].i};
            t = cmul_(t, c3);
            acc += t.r * cgv;
        }
    }
    return acc;
}

constexpr double w3j_norm_(int l1, int l2, int l3) {
    int n1 = 2*l1+1, n2 = 2*l2+1, n3 = 2*l3+1;
    double s = 0.0;
    for (int j = 0; j < n1; ++j)
        for (int l = 0; l < n2; ++l)
            for (int m = 0; m < n3; ++m) {
                double e = w3j_elem_(l1, l2, l3, j, l, m);
                s += e * e;
            }
    return csqrt_(s);
}

constexpr double N111_ = w3j_norm_(1, 1, 1);
constexpr double N121_ = w3j_norm_(1, 2, 1);

constexpr float W111(int idx) {
    return (float)(w3j_elem_(1, 1, 1, idx/9, (idx%9)/3, idx%3) / N111_);
}
constexpr float W121(int idx) {
    return (float)(w3j_elem_(1, 2, 1, idx/15, (idx%15)/3, idx%3) / N121_);
}

__constant__ float c_w3j111[27] = {
    W111(0),  W111(1),  W111(2),  W111(3),  W111(4),  W111(5),  W111(6),
    W111(7),  W111(8),  W111(9),  W111(10), W111(11), W111(12), W111(13),
    W111(14), W111(15), W111(16), W111(17), W111(18), W111(19), W111(20),
    W111(21), W111(22), W111(23), W111(24), W111(25), W111(26)
};
__constant__ float c_w3j121[45] = {
    W121(0),  W121(1),  W121(2),  W121(3),  W121(4),  W121(5),  W121(6),
    W121(7),  W121(8),  W121(9),  W121(10), W121(11), W121(12), W121(13),
    W121(14), W121(15), W121(16), W121(17), W121(18), W121(19), W121(20),
    W121(21), W121(22), W121(23), W121(24), W121(25), W121(26), W121(27),
    W121(28), W121(29), W121(30), W121(31), W121(32), W121(33), W121(34),
    W121(35), W121(36), W121(37), W121(38), W121(39), W121(40), W121(41),
    W121(42), W121(43), W121(44)
};

// ---------------------------------------------------------------------------
__device__ __forceinline__ uint32_t smem_u32(const void* p) {
    uint32_t a;
    asm("{ .reg .u64 t; cvta.to.shared.u64 t, %1; cvt.u32.u64 %0, t; }"
        : "=r"(a) : "l"(p));
    return a;
}

__device__ __forceinline__ void bulk_cp(uint32_t dst, const float* src,
                                        uint32_t bytes, uint32_t mb) {
    asm volatile(
        "cp.async.bulk.shared::cluster.global.mbarrier::complete_tx::bytes "
        "[%0], [%1], %2, [%3];"
        :: "r"(dst), "l"(src), "r"(bytes), "r"(mb) : "memory");
}

struct __align__(128) SmemLayout {
    float sw[WHALF];                // 14256 B, TMA destination
    float sx1[108];
    float sx2[12];
    float da[10];                   // A: d110   B: d213
    float ca[30];                   // A: c12    B: c112
    float cb[32];                   // A: c211   B: c22
    float sj1[27], sj2[45];
    uint64_t mbar;
};

__global__ __launch_bounds__(96, 15) void tp_kernel(
    const float* __restrict__ x1,
    const float* __restrict__ x2,
    const float* __restrict__ w,
    float* __restrict__ out,
    int nrows)
{
    extern __shared__ __align__(128) char smem_raw[];
    SmemLayout* S = reinterpret_cast<SmemLayout*>(smem_raw);

    const int tid = threadIdx.x;
    const size_t z = (size_t)(blockIdx.x >> 1);
    const bool isA = (blockIdx.x & 1u) == 0u;

    const uint32_t mbar_a = smem_u32(&S->mbar);
    const float* wrow = w + z * WTOT;

    // ---- tid 0: issue this half's 3 bulk copies at cycle 0 ----
    if (tid == 0) {
        asm volatile("mbarrier.init.shared.b64 [%0], %1;"
                     :: "r"(mbar_a), "r"(1) : "memory");
        asm volatile("fence.proxy.async.shared::cta;" ::: "memory");
        asm volatile("mbarrier.arrive.expect_tx.shared.b64 _, [%0], %1;"
                     :: "r"(mbar_a), "r"((uint32_t)(WHALF * 4)) : "memory");
        uint32_t sws = smem_u32(S->sw);
        if (isA) {
            bulk_cp(sws,             wrow,        3364u * 4u, mbar_a);
            bulk_cp(sws + 3364u*4u,  wrow + 3464,  100u * 4u, mbar_a);
            bulk_cp(sws + 3464u*4u,  wrow + 3664,  100u * 4u, mbar_a);
        } else {
            bulk_cp(sws,             wrow + 3364,  100u * 4u, mbar_a);
            bulk_cp(sws +  100u*4u,  wrow + 3564,  100u * 4u, mbar_a);
            bulk_cp(sws +  200u*4u,  wrow + 3764, 3364u * 4u, mbar_a);
        }
    }

    // ---- Dependency-free L2 prefetch of own half, PF_DIST rows ahead ----
    if (tid == 95 && z + PF_DIST < (size_t)nrows) {
        const float* pf = w + (z + PF_DIST) * WTOT + (isA ? 0 : WHALF);
        asm volatile("cp.async.bulk.prefetch.L2.global [%0], %1;"
                     :: "l"(pf), "r"((uint32_t)(WHALF * 4)) : "memory");
    }

    // ---- Small operand loads in parallel with the TMA ----
    // A keeps x1[0:108) (0e,1o,1e); B keeps x1[48:156) (1o,1e,0o).
    if (tid < 27) {
        const float4* src = reinterpret_cast<const float4*>(x1)
                          + (z * XW + (isA ? 0 : 48)) / 4;
        reinterpret_cast<float4*>(S->sx1)[tid] = src[tid];
    } else if (tid >= 32 && tid < 41) {
        S->sx2[tid - 32] = x2[z * 9 + (tid - 32)];
    }
    if (tid >= 48 && tid < 75)  S->sj1[tid - 48] = c_w3j111[tid - 48];
    if (tid >= 48 && tid < 93)  S->sj2[tid - 48] = c_w3j121[tid - 48];
    __syncthreads();

    const float* px1 = S->sx1;
    const float* px2 = S->sx2;

    // ---- Aux coefficients (under the TMA) ----
    // A: da=d110(x1_1o.x2_1o) ca=c12(x1_1o ox x2_2e) cb=c211(x1_1e ox x2_1o)
    // B: da=d213(x1_1e.x2_1o) ca=c112(x1_1o ox x2_1o) cb=c22(x1_1e ox x2_2e)
    if (tid < 10) {
        const float* p = isA ? (px1 + 48) : (px1 + 30);   // 1o vs 1e base
        float v = 0.f;
        #pragma unroll
        for (int q = 0; q < 3; q++) v += p[tid*3 + q] * px2[1 + q];
        S->da[tid] = v;
    } else if (tid < 40) {
        int t = tid - 10, u = t/3, k = t%3; float v = 0.f;
        if (isA) {      // c12: x1_1o @48, x2_2e, sj2
            #pragma unroll
            for (int q = 0; q < 3; q++)
                #pragma unroll
                for (int j = 0; j < 5; j++)
                    v += px1[48 + u*3 + q] * px2[4 + j] * S->sj2[q*15 + j*3 + k];
        } else {        // c112: x1_1o @0, x2_1o, sj1
            #pragma unroll
            for (int q = 0; q < 3; q++)
                #pragma unroll
                for (int j = 0; j < 3; j++)
                    v += px1[u*3 + q] * px2[1 + j] * S->sj1[q*9 + j*3 + k];
        }
        S->ca[t] = v;
    } else if (tid < 70) {
        int t = tid - 40, u = t/3, k = t%3; float v = 0.f;
        if (isA) {      // c211: x1_1e @78, x2_1o, sj1
            #pragma unroll
            for (int q = 0; q < 3; q++)
                #pragma unroll
                for (int j = 0; j < 3; j++)
                    v += px1[78 + u*3 + q] * px2[1 + j] * S->sj1[q*9 + j*3 + k];
        } else {        // c22: x1_1e @30, x2_2e, sj2
            #pragma unroll
            for (int q = 0; q < 3; q++)
                #pragma unroll
                for (int j = 0; j < 5; j++)
                    v += px1[30 + u*3 + q] * px2[4 + j] * S->sj2[q*15 + j*3 + k];
        }
        S->cb[t] = v;
    }
    __syncthreads();

    // ---- Wait for weights ----
    {
        uint32_t done;
        do {
            asm volatile(
                "{\n .reg .pred p;\n"
                " mbarrier.try_wait.parity.acquire.cta.shared::cta.b64 p, [%1], %2, 0x989680;\n"
                " selp.b32 %0, 1, 0, p;\n}"
                : "=r"(done) : "r"(mbar_a), "r"(0u) : "memory");
        } while (!done);
    }

    const float NORM_0E = 0.13130643285972254f;  // sqrt(1/58)
    const float NORM_1O = 0.19611613513818404f;  // sqrt(3/78)
    const float NORM_1E = 0.19611613513818404f;
    const float NORM_0O = 0.13130643285972254f;
    const float RS3     = 0.57735026918962576f;  // 1/sqrt(3)

    const float* sw = S->sw;
    float* orow = out + z * XW;

    if (isA) {
        if (tid < 48) {
            // r0e[w]: w00@0, w110@2884
            float a = 0.f;
            #pragma unroll 8
            for (int u = 0; u < 48; u++) a += px1[u] * sw[u*48 + tid];
            float bb = 0.f;
            #pragma unroll
            for (int u = 0; u < 10; u++) bb += S->da[u] * sw[2884 + u*48 + tid];
            orow[tid] = NORM_0E * (a * px2[0] + RS3 * bb);
        } else if (tid < 78) {
            // r1o[w,i]: w01@2304, w10@2784, w12@3364(local), w211@3464(local)
            int t = tid - 48, wI = t/3, i = t%3;
            float t01 = 0.f;
            #pragma unroll 8
            for (int u = 0; u < 48; u++) t01 += px1[u] * sw[2304 + u*10 + wI];
            float a10 = 0.f, a12 = 0.f, a211 = 0.f;
            #pragma unroll
            for (int u = 0; u < 10; u++) {
                a10  += px1[48 + u*3 + i] * sw[2784 + u*10 + wI];
                a12  += S->ca[u*3 + i]    * sw[3364 + u*10 + wI];
                a211 += S->cb[u*3 + i]    * sw[3464 + u*10 + wI];
            }
            orow[48 + wI*3 + i] =
                NORM_1O * (RS3 * (t01 * px2[1 + i] + px2[0] * a10) + a12 + a211);
        }
    } else {
        if (tid < 30) {
            // r1e[w,k]: w112@0, w20@100, w22@680, w31@3084 (local)
            int wI = tid/3, k = tid%3;
            float t31 = 0.f;
            #pragma unroll 8
            for (int u = 0; u < 48; u++) t31 += px1[60 + u] * sw[3084 + u*10 + wI];
            float a112 = 0.f, a20 = 0.f, a22 = 0.f;
            #pragma unroll
            for (int u = 0; u < 10; u++) {
                a112 += S->ca[u*3 + k]    * sw[u*10 + wI];
                a20  += px1[30 + u*3 + k] * sw[100 + u*10 + wI];
                a22  += S->cb[u*3 + k]    * sw[680 + u*10 + wI];
            }
            orow[78 + wI*3 + k] =
                NORM_1E * (a112 + RS3 * (px2[0] * a20 + t31 * px2[1 + k]) + a22);
        } else if (tid < 78) {
            // r0o[w]: w213@200, w30@780 (local); x1_0o @ px1[60]
            int wI = tid - 30;
            float a = 0.f;
            #pragma unroll
            for (int u = 0; u < 10; u++) a += S->da[u] * sw[200 + u*48 + wI];
            float bb = 0.f;
            #pragma unroll 8
            for (int u = 0; u < 48; u++) bb += px1[60 + u] * sw[780 + u*48 + wI];
            orow[108 + wI] = NORM_0O * (RS3 * a + bb * px2[0]);
        }
    }
}

// ---------------------------------------------------------------------------
extern "C" void kernel_launch(void* const* d_in, const int* in_sizes, int n_in,
                              void* d_out, int out_size)
{
    const float* x1 = (const float*)d_in[0];
    const float* x2 = (const float*)d_in[1];
    const float* w  = (const float*)d_in[2];
    float* out = (float*)d_out;

    int B = in_sizes[1] / 9;   // x2 has 9 floats per row
    int smem_bytes = (int)sizeof(SmemLayout);

    cudaFuncSetAttribute(tp_kernel,
                         cudaFuncAttributeMaxDynamicSharedMemorySize, smem_bytes);

    tp_kernel<<<2 * B, 96, smem_bytes>>>(x1, x2, w, out, B);
}